// round 14
// baseline (speedup 1.0000x reference)
#include <cuda_runtime.h>
#include <cuda_fp16.h>

#define NN 100000
#define EE 1600000
#define NB 148
#define NT 1024
#define GSZ (NB * NT)
#define CHUNK 676            // ceil(NN/NB)
#define WT_STRIDE 72
#define WT_SZ (64 * WT_STRIDE)
#define W2_SZ (16 * WT_STRIDE)
#define TILE 256
#define NTILES 391           // ceil(NN/256)

// dynamic smem layout (bytes)
#define SM_XS0 0
#define SM_XS1 36864
#define SM_WT  73728
#define SM_W2  82944
#define SM_BS1 85248
#define SM_BS2 85504
#define SM_TOTAL 85568

// ---------------- device globals ---------------------------------------------
__device__ __half g_h[NN * 64];
__device__ __half g_f[NN * 64];
__device__ __half g_wt[5 * WT_SZ];
__device__ float  g_dinv[NN];
__device__ int    g_deg[NN];
__device__ int    g_off[NN + 1];
__device__ int    g_cur[NN];
// int4-typed so the base is 16B-aligned (LDG.128 in agg). One int4 = edge PAIR.
__device__ int4   g_epack4[(EE + NN) / 2 + 8];
#define g_epack ((int2*)g_epack4)
__device__ int    g_bsum[NB];
__device__ unsigned g_cnt;
__device__ volatile unsigned g_gen;

// ---------------- grid barrier ------------------------------------------------
__device__ __forceinline__ void gbar() {
    __syncthreads();
    if (threadIdx.x == 0) {
        unsigned gen = g_gen;
        __threadfence();
        unsigned t = atomicAdd(&g_cnt, 1u);
        if (t == NB - 1u) {
            g_cnt = 0u;
            __threadfence();
            g_gen = gen + 1u;
        } else {
            while (g_gen == gen) __nanosleep(32);
        }
    }
    __syncthreads();
}

// ---------------- warp 16x32 mma (rows mt.., cols nb..nb+31) ------------------
__device__ __forceinline__ void mma_16x32(const __half* xs, const __half* wt,
                                          __half* Y, int rowBlock,
                                          int mt, int nb, int qr, int qc) {
    float c[4][4];
#pragma unroll
    for (int j = 0; j < 4; j++)
#pragma unroll
        for (int q = 0; q < 4; q++) c[j][q] = 0.f;

#pragma unroll
    for (int ks = 0; ks < 4; ks++) {
        int k0 = ks * 16;
        unsigned a0 = *(const unsigned*)&xs[(mt + qr) * WT_STRIDE + k0 + qc];
        unsigned a1 = *(const unsigned*)&xs[(mt + qr + 8) * WT_STRIDE + k0 + qc];
        unsigned a2 = *(const unsigned*)&xs[(mt + qr) * WT_STRIDE + k0 + qc + 8];
        unsigned a3 = *(const unsigned*)&xs[(mt + qr + 8) * WT_STRIDE + k0 + qc + 8];
#pragma unroll
        for (int j = 0; j < 4; j++) {
            int n = nb + j * 8 + qr;
            unsigned b0 = *(const unsigned*)&wt[n * WT_STRIDE + k0 + qc];
            unsigned b1 = *(const unsigned*)&wt[n * WT_STRIDE + k0 + qc + 8];
            asm volatile(
                "mma.sync.aligned.m16n8k16.row.col.f32.f16.f16.f32 "
                "{%0,%1,%2,%3}, {%4,%5,%6,%7}, {%8,%9}, {%0,%1,%2,%3};"
                : "+f"(c[j][0]), "+f"(c[j][1]), "+f"(c[j][2]), "+f"(c[j][3])
                : "r"(a0), "r"(a1), "r"(a2), "r"(a3), "r"(b0), "r"(b1));
        }
    }
    int gr0 = rowBlock + mt + qr;
    int gr1 = gr0 + 8;
#pragma unroll
    for (int j = 0; j < 4; j++) {
        int n0 = nb + j * 8;
        if (gr0 < NN)
            *(__half2*)&Y[(size_t)gr0 * 64 + n0 + qc] = __floats2half2_rn(c[j][0], c[j][1]);
        if (gr1 < NN)
            *(__half2*)&Y[(size_t)gr1 * 64 + n0 + qc] = __floats2half2_rn(c[j][2], c[j][3]);
    }
}

// ---------------- gemm phase: 256-row tiles, double-buffered ------------------
template <bool IN32>
__device__ void gemm_phase(const void* Xv, const __half* wtg, __half* Y, char* sm) {
    __half* xs0 = (__half*)(sm + SM_XS0);
    __half* xs1 = (__half*)(sm + SM_XS1);
    __half* wt  = (__half*)(sm + SM_WT);
    int tid = threadIdx.x;
    for (int i = tid; i < WT_SZ / 8; i += NT)
        ((uint4*)wt)[i] = ((const uint4*)wtg)[i];

    int lane = tid & 31, w = tid >> 5;
    int mt = (w >> 1) * 16;
    int nb = (w & 1) * 32;
    int qr = lane >> 2, qc = (lane & 3) * 2;

    int tile = blockIdx.x;
    if (tile < NTILES) {
        if (IN32) {
            const float4* X4 = (const float4*)Xv;
#pragma unroll
            for (int k = 0; k < 4; k++) {
                int idx = tid + k * NT;
                int row = idx >> 4, c4 = idx & 15;
                int gr = tile * TILE + row;
                float4 v = (gr < NN) ? X4[(size_t)gr * 16 + c4]
                                     : make_float4(0.f, 0.f, 0.f, 0.f);
                __half2 h0 = __floats2half2_rn(v.x, v.y);
                __half2 h1 = __floats2half2_rn(v.z, v.w);
                uint2 u; u.x = *(unsigned*)&h0; u.y = *(unsigned*)&h1;
                *(uint2*)&xs0[row * WT_STRIDE + c4 * 4] = u;
            }
        } else {
            const uint4* X4 = (const uint4*)Xv;
#pragma unroll
            for (int k = 0; k < 2; k++) {
                int idx = tid + k * NT;
                int row = idx >> 3, c8 = idx & 7;
                int gr = tile * TILE + row;
                uint4 u = (gr < NN) ? __ldcg(X4 + (size_t)gr * 8 + c8)
                                    : make_uint4(0u, 0u, 0u, 0u);
                *(uint4*)&xs0[row * WT_STRIDE + c8 * 8] = u;
            }
        }
    }
    __syncthreads();

    int buf = 0;
    for (; tile < NTILES; tile += NB) {
        int nxt = tile + NB;
        bool has = nxt < NTILES;
        float4 s32[4];
        uint4  s16[2];
        if (has) {
            if (IN32) {
                const float4* X4 = (const float4*)Xv;
#pragma unroll
                for (int k = 0; k < 4; k++) {
                    int idx = tid + k * NT;
                    int row = idx >> 4, c4 = idx & 15;
                    int gr = nxt * TILE + row;
                    s32[k] = (gr < NN) ? X4[(size_t)gr * 16 + c4]
                                       : make_float4(0.f, 0.f, 0.f, 0.f);
                }
            } else {
                const uint4* X4 = (const uint4*)Xv;
#pragma unroll
                for (int k = 0; k < 2; k++) {
                    int idx = tid + k * NT;
                    int row = idx >> 3, c8 = idx & 7;
                    int gr = nxt * TILE + row;
                    s16[k] = (gr < NN) ? __ldcg(X4 + (size_t)gr * 8 + c8)
                                       : make_uint4(0u, 0u, 0u, 0u);
                }
            }
        }
        const __half* cur = buf ? xs1 : xs0;
        mma_16x32(cur, wt, Y, tile * TILE, mt, nb, qr, qc);
        if (has) {
            __half* oth = buf ? xs0 : xs1;
            if (IN32) {
#pragma unroll
                for (int k = 0; k < 4; k++) {
                    int idx = tid + k * NT;
                    int row = idx >> 4, c4 = idx & 15;
                    __half2 h0 = __floats2half2_rn(s32[k].x, s32[k].y);
                    __half2 h1 = __floats2half2_rn(s32[k].z, s32[k].w);
                    uint2 u; u.x = *(unsigned*)&h0; u.y = *(unsigned*)&h1;
                    *(uint2*)&oth[row * WT_STRIDE + c4 * 4] = u;
                }
            } else {
#pragma unroll
                for (int k = 0; k < 2; k++) {
                    int idx = tid + k * NT;
                    int row = idx >> 3, c8 = idx & 7;
                    *(uint4*)&oth[row * WT_STRIDE + c8 * 8] = s16[k];
                }
            }
        }
        __syncthreads();
        buf ^= 1;
    }
}

// ---------------- agg phase: wide loads, half-warp edge split -----------------
__device__ void agg_phase(const __half* h, __half* outp, const float* bias) {
    int gw = (blockIdx.x * NT + threadIdx.x) >> 5;
    int lane = threadIdx.x & 31;
    int hi = lane >> 4;          // 0: even edge of pair, 1: odd
    int l16 = lane & 15;
    const int NW = GSZ / 32;
    float4 bias4 = ((const float4*)bias)[l16];

    for (int w = gw; w < NN; w += NW) {
        int e0 = g_off[w];                  // even
        int npairs = (g_off[w + 1] - e0) >> 1;
        const int4* ep = g_epack4 + (e0 >> 1);
        float a0 = 0.f, a1 = 0.f, a2 = 0.f, a3 = 0.f;

        for (int pc = 0; pc < npairs; pc += 4) {
            int4 p[4];
#pragma unroll
            for (int j = 0; j < 4; j++) {
                int idx = pc + j;
                p[j] = ep[idx < npairs ? idx : npairs - 1];
            }
            uint2 r[4];
            float cf[4];
#pragma unroll
            for (int j = 0; j < 4; j++) {
                int src = hi ? p[j].z : p[j].x;
                float c = __int_as_float(hi ? p[j].w : p[j].y);
                cf[j] = (pc + j < npairs) ? c : 0.f;
                r[j] = __ldcg((const uint2*)(h + (size_t)src * 64) + l16);
            }
#pragma unroll
            for (int j = 0; j < 4; j++) {
                float2 f0 = __half22float2(*(__half2*)&r[j].x);
                float2 f1 = __half22float2(*(__half2*)&r[j].y);
                a0 = fmaf(f0.x, cf[j], a0);
                a1 = fmaf(f0.y, cf[j], a1);
                a2 = fmaf(f1.x, cf[j], a2);
                a3 = fmaf(f1.y, cf[j], a3);
            }
        }
        a0 += __shfl_xor_sync(0xFFFFFFFFu, a0, 16);
        a1 += __shfl_xor_sync(0xFFFFFFFFu, a1, 16);
        a2 += __shfl_xor_sync(0xFFFFFFFFu, a2, 16);
        a3 += __shfl_xor_sync(0xFFFFFFFFu, a3, 16);

        float dn = g_dinv[w];
        float d2 = dn * dn;
        uint2 su = __ldcg((const uint2*)(h + (size_t)w * 64) + l16);
        float2 s0 = __half22float2(*(__half2*)&su.x);
        float2 s1 = __half22float2(*(__half2*)&su.y);
        a0 = fmaf(s0.x, d2, a0) + bias4.x;
        a1 = fmaf(s0.y, d2, a1) + bias4.y;
        a2 = fmaf(s1.x, d2, a2) + bias4.z;
        a3 = fmaf(s1.y, d2, a3) + bias4.w;
        if (lane < 16) {
            __half2 h0 = __floats2half2_rn(fmaxf(a0, 0.f), fmaxf(a1, 0.f));
            __half2 h1 = __floats2half2_rn(fmaxf(a2, 0.f), fmaxf(a3, 0.f));
            uint2 o; o.x = *(unsigned*)&h0; o.y = *(unsigned*)&h1;
            *((uint2*)(outp + (size_t)w * 64) + l16) = o;
        }
    }
}

// ---------------- ffn phase: 256-row tiles (R11 geometry) ---------------------
__device__ void ffn_phase(const __half* Xh, const __half* wt1g, const __half* wt2g,
                          const float* b1f, const float* b2f, float* Y, char* sm) {
    __half* xs = (__half*)(sm + SM_XS0);
    __half* w1 = (__half*)(sm + SM_WT);
    __half* w2 = (__half*)(sm + SM_W2);
    float* bs1 = (float*)(sm + SM_BS1);
    float* bs2 = (float*)(sm + SM_BS2);
    int tid = threadIdx.x;
    for (int i = tid; i < WT_SZ / 8; i += NT)
        ((uint4*)w1)[i] = ((const uint4*)wt1g)[i];
    if (tid < W2_SZ / 8) ((uint4*)w2)[tid] = ((const uint4*)wt2g)[tid];
    if (tid < 64) bs1[tid] = b1f[tid];
    if (tid < 16) bs2[tid] = b2f[tid];

    int lane = tid & 31, w = tid >> 5;
    int mt = (w >> 1) * 16;
    int nb = (w & 1) * 32;
    int qr = lane >> 2, qc = (lane & 3) * 2;

    for (int tile = blockIdx.x; tile < NTILES; tile += NB) {
        int rowBlock = tile * TILE;
        __syncthreads();                   // xs safe to overwrite
        {
            const uint4* X4 = (const uint4*)Xh;
#pragma unroll
            for (int k = 0; k < 2; k++) {
                int idx = tid + k * NT;
                int row = idx >> 3, c8 = idx & 7;
                int gr = rowBlock + row;
                uint4 u = (gr < NN) ? __ldcg(X4 + (size_t)gr * 8 + c8)
                                    : make_uint4(0u, 0u, 0u, 0u);
                *(uint4*)&xs[row * WT_STRIDE + c8 * 8] = u;
            }
        }
        __syncthreads();

        // phase 1: H = X @ Wf1 (warp: 16 rows x 32 cols)
        float c[4][4];
#pragma unroll
        for (int j = 0; j < 4; j++)
#pragma unroll
            for (int q = 0; q < 4; q++) c[j][q] = 0.f;
#pragma unroll
        for (int ks = 0; ks < 4; ks++) {
            int k0 = ks * 16;
            unsigned a0 = *(const unsigned*)&xs[(mt + qr) * WT_STRIDE + k0 + qc];
            unsigned a1 = *(const unsigned*)&xs[(mt + qr + 8) * WT_STRIDE + k0 + qc];
            unsigned a2 = *(const unsigned*)&xs[(mt + qr) * WT_STRIDE + k0 + qc + 8];
            unsigned a3 = *(const unsigned*)&xs[(mt + qr + 8) * WT_STRIDE + k0 + qc + 8];
#pragma unroll
            for (int j = 0; j < 4; j++) {
                int n = nb + j * 8 + qr;
                unsigned b0 = *(const unsigned*)&w1[n * WT_STRIDE + k0 + qc];
                unsigned b1 = *(const unsigned*)&w1[n * WT_STRIDE + k0 + qc + 8];
                asm volatile(
                    "mma.sync.aligned.m16n8k16.row.col.f32.f16.f16.f32 "
                    "{%0,%1,%2,%3}, {%4,%5,%6,%7}, {%8,%9}, {%0,%1,%2,%3};"
                    : "+f"(c[j][0]), "+f"(c[j][1]), "+f"(c[j][2]), "+f"(c[j][3])
                    : "r"(a0), "r"(a1), "r"(a2), "r"(a3), "r"(b0), "r"(b1));
            }
        }
        __syncthreads();                   // all reads of xs done
#pragma unroll
        for (int j = 0; j < 4; j++) {
            int n0 = nb + j * 8;
            float v0 = fmaxf(c[j][0] + bs1[n0 + qc], 0.f);
            float v1 = fmaxf(c[j][1] + bs1[n0 + qc + 1], 0.f);
            float v2 = fmaxf(c[j][2] + bs1[n0 + qc], 0.f);
            float v3 = fmaxf(c[j][3] + bs1[n0 + qc + 1], 0.f);
            *(__half2*)&xs[(mt + qr) * WT_STRIDE + n0 + qc] = __floats2half2_rn(v0, v1);
            *(__half2*)&xs[(mt + qr + 8) * WT_STRIDE + n0 + qc] = __floats2half2_rn(v2, v3);
        }
        __syncthreads();

        // phase 2: Y = H @ Wf2 + bf2 (n=16; even warp cols 0-7, odd 8-15)
        float d[4] = {0.f, 0.f, 0.f, 0.f};
        int n0 = (w & 1) * 8;
#pragma unroll
        for (int ks = 0; ks < 4; ks++) {
            int k0 = ks * 16;
            unsigned a0 = *(const unsigned*)&xs[(mt + qr) * WT_STRIDE + k0 + qc];
            unsigned a1 = *(const unsigned*)&xs[(mt + qr + 8) * WT_STRIDE + k0 + qc];
            unsigned a2 = *(const unsigned*)&xs[(mt + qr) * WT_STRIDE + k0 + qc + 8];
            unsigned a3 = *(const unsigned*)&xs[(mt + qr + 8) * WT_STRIDE + k0 + qc + 8];
            unsigned b0 = *(const unsigned*)&w2[(n0 + qr) * WT_STRIDE + k0 + qc];
            unsigned b1 = *(const unsigned*)&w2[(n0 + qr) * WT_STRIDE + k0 + qc + 8];
            asm volatile(
                "mma.sync.aligned.m16n8k16.row.col.f32.f16.f16.f32 "
                "{%0,%1,%2,%3}, {%4,%5,%6,%7}, {%8,%9}, {%0,%1,%2,%3};"
                : "+f"(d[0]), "+f"(d[1]), "+f"(d[2]), "+f"(d[3])
                : "r"(a0), "r"(a1), "r"(a2), "r"(a3), "r"(b0), "r"(b1));
        }
        int gr0 = rowBlock + mt + qr;
        int gr1 = gr0 + 8;
        if (gr0 < NN)
            *(float2*)&Y[(size_t)gr0 * 16 + n0 + qc] =
                make_float2(d[0] + bs2[n0 + qc], d[1] + bs2[n0 + qc + 1]);
        if (gr1 < NN)
            *(float2*)&Y[(size_t)gr1 * 16 + n0 + qc] =
                make_float2(d[2] + bs2[n0 + qc], d[3] + bs2[n0 + qc + 1]);
    }
}

// ---------------- mega kernel -------------------------------------------------
__global__ __launch_bounds__(NT, 1) void k_mega(
    const float* __restrict__ x, const int* __restrict__ ei,
    const float* __restrict__ W1, const float* __restrict__ b1,
    const float* __restrict__ W2, const float* __restrict__ b2,
    const float* __restrict__ W3, const float* __restrict__ b3,
    const float* __restrict__ Wf1, const float* __restrict__ bf1,
    const float* __restrict__ Wf2, const float* __restrict__ bf2,
    float* __restrict__ out) {
    extern __shared__ char sm[];
    int tid = threadIdx.x;
    int cta = blockIdx.x;
    int gtid = cta * NT + tid;
    int lane = tid & 31, wrp = tid >> 5;

    // ---- P0: weight prep + degree count ----
    for (int t = gtid; t < 4 * 4096 + 1024; t += GSZ) {
        if (t < 4 * 4096) {
            int w = t >> 12, i = t & 4095, k = i >> 6, n = i & 63;
            const float* src = (w == 0) ? W1 : (w == 1) ? W2 : (w == 2) ? W3 : Wf1;
            g_wt[w * WT_SZ + n * WT_STRIDE + k] = __float2half(src[k * 64 + n]);
        } else {
            int i = t - 4 * 4096;
            int k = i >> 4, n = i & 15;
            g_wt[4 * WT_SZ + n * WT_STRIDE + k] = __float2half(Wf2[k * 16 + n]);
        }
    }
    {
        const int4* d4 = (const int4*)(ei + EE);
        for (int t = gtid; t < EE / 4; t += GSZ) {
            int4 d = d4[t];
            atomicAdd(&g_deg[d.x], 1);
            atomicAdd(&g_deg[d.y], 1);
            atomicAdd(&g_deg[d.z], 1);
            atomicAdd(&g_deg[d.w], 1);
        }
    }
    gbar();

    // ---- P1: per-CTA inclusive scan over even-padded lengths ----
    __shared__ int wsum[32];
    __shared__ int s_ctaoff;
    int node = cta * CHUNK + tid;
    int dg = (tid < CHUNK && node < NN) ? g_deg[node] : 0;
    int pl = (dg + 1) & ~1;
    int incl = pl;
#pragma unroll
    for (int off = 1; off < 32; off <<= 1) {
        int t = __shfl_up_sync(0xFFFFFFFFu, incl, off);
        if (lane >= off) incl += t;
    }
    if (lane == 31) wsum[wrp] = incl;
    __syncthreads();
    if (wrp == 0) {
        int v = wsum[lane];
        int iv = v;
#pragma unroll
        for (int off = 1; off < 32; off <<= 1) {
            int t = __shfl_up_sync(0xFFFFFFFFu, iv, off);
            if (lane >= off) iv += t;
        }
        wsum[lane] = iv;
    }
    __syncthreads();
    if (wrp > 0) incl += wsum[wrp - 1];
    if (tid == 0) g_bsum[cta] = wsum[31];
    gbar();

    // ---- P2: cross-CTA offset + write off/cur/dinv ----
    {
        int v = (tid < cta) ? g_bsum[tid] : 0;
#pragma unroll
        for (int off = 16; off > 0; off >>= 1)
            v += __shfl_down_sync(0xFFFFFFFFu, v, off);
        __shared__ int rsum[32];
        if (lane == 0) rsum[wrp] = v;
        __syncthreads();
        if (tid == 0) {
            int t = 0;
#pragma unroll
            for (int i = 0; i < 32; i++) t += rsum[i];
            s_ctaoff = t;
        }
        __syncthreads();
    }
    int excl = s_ctaoff + incl - pl;
    if (tid < CHUNK && node < NN) {
        g_off[node] = excl;
        g_cur[node] = excl;
        g_dinv[node] = rsqrtf((float)dg + 1.0f);
    }
    if (cta == 0 && tid == 0) {
        int t = 0;
        for (int i = 0; i < NB; i++) t += g_bsum[i];
        g_off[NN] = t;
    }
    gbar();

    // ---- P3: fill CSR + pads + re-zero deg ----
    for (int e = gtid; e < EE; e += GSZ) {
        int s = ei[e];
        int d = ei[EE + e];
        int p = atomicAdd(&g_cur[d], 1);
        float c = g_dinv[s] * g_dinv[d];
        g_epack[p] = make_int2(s, __float_as_int(c));
    }
    for (int n = gtid; n < NN; n += GSZ) {
        int dg2 = g_deg[n];
        if (dg2 & 1) g_epack[g_off[n] + dg2] = make_int2(0, 0);
        g_deg[n] = 0;
    }
    gbar();

    // ---- layers ----
    gemm_phase<true>(x, g_wt + 0 * WT_SZ, g_h, sm);
    gbar();
    agg_phase(g_h, g_f, b1);
    gbar();
    gemm_phase<false>(g_f, g_wt + 1 * WT_SZ, g_h, sm);
    gbar();
    agg_phase(g_h, g_f, b2);
    gbar();
    gemm_phase<false>(g_f, g_wt + 2 * WT_SZ, g_h, sm);
    gbar();
    agg_phase(g_h, g_f, b3);
    gbar();
    ffn_phase(g_f, g_wt + 3 * WT_SZ, g_wt + 4 * WT_SZ, bf1, bf2, out, sm);
}

// ---------------- launch ------------------------------------------------------
extern "C" void kernel_launch(void* const* d_in, const int* in_sizes, int n_in,
                              void* d_out, int out_size) {
    const float* x   = (const float*)d_in[0];
    const int*   ei  = (const int*)d_in[1];
    const float* W1  = (const float*)d_in[2];
    const float* b1  = (const float*)d_in[3];
    const float* W2  = (const float*)d_in[4];
    const float* b2  = (const float*)d_in[5];
    const float* W3  = (const float*)d_in[6];
    const float* b3  = (const float*)d_in[7];
    const float* Wf1 = (const float*)d_in[8];
    const float* bf1 = (const float*)d_in[9];
    const float* Wf2 = (const float*)d_in[10];
    const float* bf2 = (const float*)d_in[11];
    float* out = (float*)d_out;

    static bool attr_set = false;
    if (!attr_set) {
        cudaFuncSetAttribute(k_mega, cudaFuncAttributeMaxDynamicSharedMemorySize,
                             SM_TOTAL);
        attr_set = true;
    }
    k_mega<<<NB, NT, SM_TOTAL>>>(x, ei, W1, b1, W2, b2, W3, b3,
                                 Wf1, bf1, Wf2, bf2, out);
}

// round 15
// speedup vs baseline: 1.2279x; 1.2279x over previous
#include <cuda_runtime.h>
#include <cuda_fp16.h>

#define NN 100000
#define EE 1600000
#define NB 148
#define NT 1024
#define GSZ (NB * NT)
#define CHUNK 676            // ceil(NN/NB)
#define WT_STRIDE 72
#define WT_SZ (64 * WT_STRIDE)
#define W2_SZ (16 * WT_STRIDE)
#define TILE 256
#define NTILES 391           // ceil(NN/256)

// dynamic smem layout (bytes)
#define SM_XS0 0
#define SM_XS1 36864
#define SM_WT  73728
#define SM_W2  82944
#define SM_BS1 85248
#define SM_BS2 85504
#define SM_TOTAL 85568

// ---------------- device globals ---------------------------------------------
__device__ __half g_h[NN * 64];     // gemm out -> agg in
__device__ __half g_f[NN * 64];     // (converted x) / agg out -> gemm in
__device__ __half g_wt[5 * WT_SZ];
__device__ float  g_dinv[NN];
__device__ int    g_deg[NN];
__device__ int    g_off[NN + 1];
__device__ int    g_cur[NN];
// int4-typed: 16B-aligned base for LDG.128. One int4 = edge PAIR (s0,c0,s1,c1).
__device__ int4   g_epack4[(EE + NN) / 2 + 8];
#define g_epack ((int2*)g_epack4)
__device__ int    g_bsum[NB];
__device__ unsigned g_cnt;
__device__ volatile unsigned g_gen;

// ---------------- grid barrier ------------------------------------------------
__device__ __forceinline__ void gbar() {
    __syncthreads();
    if (threadIdx.x == 0) {
        unsigned gen = g_gen;
        __threadfence();
        unsigned t = atomicAdd(&g_cnt, 1u);
        if (t == NB - 1u) {
            g_cnt = 0u;
            __threadfence();
            g_gen = gen + 1u;
        } else {
            while (g_gen == gen) __nanosleep(32);
        }
    }
    __syncthreads();
}

// ---------------- warp 16x32 mma (rows mt.., cols nb..nb+31) ------------------
__device__ __forceinline__ void mma_16x32(const __half* xs, const __half* wt,
                                          __half* Y, int rowBlock,
                                          int mt, int nb, int qr, int qc) {
    float c[4][4];
#pragma unroll
    for (int j = 0; j < 4; j++)
#pragma unroll
        for (int q = 0; q < 4; q++) c[j][q] = 0.f;

#pragma unroll
    for (int ks = 0; ks < 4; ks++) {
        int k0 = ks * 16;
        unsigned a0 = *(const unsigned*)&xs[(mt + qr) * WT_STRIDE + k0 + qc];
        unsigned a1 = *(const unsigned*)&xs[(mt + qr + 8) * WT_STRIDE + k0 + qc];
        unsigned a2 = *(const unsigned*)&xs[(mt + qr) * WT_STRIDE + k0 + qc + 8];
        unsigned a3 = *(const unsigned*)&xs[(mt + qr + 8) * WT_STRIDE + k0 + qc + 8];
#pragma unroll
        for (int j = 0; j < 4; j++) {
            int n = nb + j * 8 + qr;
            unsigned b0 = *(const unsigned*)&wt[n * WT_STRIDE + k0 + qc];
            unsigned b1 = *(const unsigned*)&wt[n * WT_STRIDE + k0 + qc + 8];
            asm volatile(
                "mma.sync.aligned.m16n8k16.row.col.f32.f16.f16.f32 "
                "{%0,%1,%2,%3}, {%4,%5,%6,%7}, {%8,%9}, {%0,%1,%2,%3};"
                : "+f"(c[j][0]), "+f"(c[j][1]), "+f"(c[j][2]), "+f"(c[j][3])
                : "r"(a0), "r"(a1), "r"(a2), "r"(a3), "r"(b0), "r"(b1));
        }
    }
    int gr0 = rowBlock + mt + qr;
    int gr1 = gr0 + 8;
#pragma unroll
    for (int j = 0; j < 4; j++) {
        int n0 = nb + j * 8;
        if (gr0 < NN)
            *(__half2*)&Y[(size_t)gr0 * 64 + n0 + qc] = __floats2half2_rn(c[j][0], c[j][1]);
        if (gr1 < NN)
            *(__half2*)&Y[(size_t)gr1 * 64 + n0 + qc] = __floats2half2_rn(c[j][2], c[j][3]);
    }
}

// ---------------- gemm phase: fp16 in (g_f), 256-row tiles, double-buffered ---
__device__ void gemm_phase(const __half* Xh, const __half* wtg, __half* Y, char* sm) {
    __half* xs0 = (__half*)(sm + SM_XS0);
    __half* xs1 = (__half*)(sm + SM_XS1);
    __half* wt  = (__half*)(sm + SM_WT);
    int tid = threadIdx.x;
    for (int i = tid; i < WT_SZ / 8; i += NT)
        ((uint4*)wt)[i] = ((const uint4*)wtg)[i];

    int lane = tid & 31, w = tid >> 5;
    int mt = (w >> 1) * 16;
    int nb = (w & 1) * 32;
    int qr = lane >> 2, qc = (lane & 3) * 2;

    const uint4* X4 = (const uint4*)Xh;
    int tile = blockIdx.x;
    if (tile < NTILES) {
#pragma unroll
        for (int k = 0; k < 2; k++) {
            int idx = tid + k * NT;
            int row = idx >> 3, c8 = idx & 7;
            int gr = tile * TILE + row;
            uint4 u = (gr < NN) ? __ldcg(X4 + (size_t)gr * 8 + c8)
                                : make_uint4(0u, 0u, 0u, 0u);
            *(uint4*)&xs0[row * WT_STRIDE + c8 * 8] = u;
        }
    }
    __syncthreads();

    int buf = 0;
    for (; tile < NTILES; tile += NB) {
        int nxt = tile + NB;
        bool has = nxt < NTILES;
        uint4 s16[2];
        if (has) {
#pragma unroll
            for (int k = 0; k < 2; k++) {
                int idx = tid + k * NT;
                int row = idx >> 3, c8 = idx & 7;
                int gr = nxt * TILE + row;
                s16[k] = (gr < NN) ? __ldcg(X4 + (size_t)gr * 8 + c8)
                                   : make_uint4(0u, 0u, 0u, 0u);
            }
        }
        const __half* cur = buf ? xs1 : xs0;
        mma_16x32(cur, wt, Y, tile * TILE, mt, nb, qr, qc);
        if (has) {
            __half* oth = buf ? xs0 : xs1;
#pragma unroll
            for (int k = 0; k < 2; k++) {
                int idx = tid + k * NT;
                int row = idx >> 3, c8 = idx & 7;
                *(uint4*)&oth[row * WT_STRIDE + c8 * 8] = s16[k];
            }
        }
        __syncthreads();
        buf ^= 1;
    }
}

// ---------------- agg phase: quarter-warp per node, uint4 row loads -----------
__device__ void agg_phase(const __half* h, __half* outp, const float* bias) {
    int gq = (blockIdx.x * NT + threadIdx.x) >> 3;   // quarter-warp id
    int l8 = threadIdx.x & 7;
    const int NQ = GSZ / 8;
    float4 bA = ((const float4*)bias)[l8 * 2];
    float4 bB = ((const float4*)bias)[l8 * 2 + 1];

    for (int w = gq; w < NN; w += NQ) {
        int e0 = g_off[w];
        int npairs = (g_off[w + 1] - e0) >> 1;
        const int4* ep = g_epack4 + (e0 >> 1);
        float a0 = 0.f, a1 = 0.f, a2 = 0.f, a3 = 0.f;
        float a4 = 0.f, a5 = 0.f, a6 = 0.f, a7 = 0.f;

        for (int pc = 0; pc < npairs; pc += 2) {
            int4 p0 = ep[pc];
            int4 p1 = ep[(pc + 1 < npairs) ? pc + 1 : pc];
            float c0 = __int_as_float(p0.y);           // pads carry coef 0
            float c1 = __int_as_float(p0.w);
            float c2 = (pc + 1 < npairs) ? __int_as_float(p1.y) : 0.f;
            float c3 = (pc + 1 < npairs) ? __int_as_float(p1.w) : 0.f;
            uint4 r0 = __ldcg((const uint4*)(h + (size_t)p0.x * 64) + l8);
            uint4 r1 = __ldcg((const uint4*)(h + (size_t)p0.z * 64) + l8);
            uint4 r2 = __ldcg((const uint4*)(h + (size_t)p1.x * 64) + l8);
            uint4 r3 = __ldcg((const uint4*)(h + (size_t)p1.z * 64) + l8);
#define ACC(r, c) do {                                               \
            float2 f0 = __half22float2(*(__half2*)&(r).x);           \
            float2 f1 = __half22float2(*(__half2*)&(r).y);           \
            float2 f2 = __half22float2(*(__half2*)&(r).z);           \
            float2 f3 = __half22float2(*(__half2*)&(r).w);           \
            a0 = fmaf(f0.x, (c), a0); a1 = fmaf(f0.y, (c), a1);      \
            a2 = fmaf(f1.x, (c), a2); a3 = fmaf(f1.y, (c), a3);      \
            a4 = fmaf(f2.x, (c), a4); a5 = fmaf(f2.y, (c), a5);      \
            a6 = fmaf(f3.x, (c), a6); a7 = fmaf(f3.y, (c), a7);      \
        } while (0)
            ACC(r0, c0);
            ACC(r1, c1);
            ACC(r2, c2);
            ACC(r3, c3);
        }

        float dn = g_dinv[w];
        float d2 = dn * dn;
        uint4 su = __ldcg((const uint4*)(h + (size_t)w * 64) + l8);
        ACC(su, d2);
#undef ACC
        a0 += bA.x; a1 += bA.y; a2 += bA.z; a3 += bA.w;
        a4 += bB.x; a5 += bB.y; a6 += bB.z; a7 += bB.w;
        __half2 h0 = __floats2half2_rn(fmaxf(a0, 0.f), fmaxf(a1, 0.f));
        __half2 h1 = __floats2half2_rn(fmaxf(a2, 0.f), fmaxf(a3, 0.f));
        __half2 h2 = __floats2half2_rn(fmaxf(a4, 0.f), fmaxf(a5, 0.f));
        __half2 h3 = __floats2half2_rn(fmaxf(a6, 0.f), fmaxf(a7, 0.f));
        uint4 o;
        o.x = *(unsigned*)&h0; o.y = *(unsigned*)&h1;
        o.z = *(unsigned*)&h2; o.w = *(unsigned*)&h3;
        *((uint4*)(outp + (size_t)w * 64) + l8) = o;
    }
}

// ---------------- ffn phase: 256-row tiles ------------------------------------
__device__ void ffn_phase(const __half* Xh, const __half* wt1g, const __half* wt2g,
                          const float* b1f, const float* b2f, float* Y, char* sm) {
    __half* xs = (__half*)(sm + SM_XS0);
    __half* w1 = (__half*)(sm + SM_WT);
    __half* w2 = (__half*)(sm + SM_W2);
    float* bs1 = (float*)(sm + SM_BS1);
    float* bs2 = (float*)(sm + SM_BS2);
    int tid = threadIdx.x;
    for (int i = tid; i < WT_SZ / 8; i += NT)
        ((uint4*)w1)[i] = ((const uint4*)wt1g)[i];
    if (tid < W2_SZ / 8) ((uint4*)w2)[tid] = ((const uint4*)wt2g)[tid];
    if (tid < 64) bs1[tid] = b1f[tid];
    if (tid < 16) bs2[tid] = b2f[tid];

    int lane = tid & 31, w = tid >> 5;
    int mt = (w >> 1) * 16;
    int nb = (w & 1) * 32;
    int qr = lane >> 2, qc = (lane & 3) * 2;

    for (int tile = blockIdx.x; tile < NTILES; tile += NB) {
        int rowBlock = tile * TILE;
        __syncthreads();
        {
            const uint4* X4 = (const uint4*)Xh;
#pragma unroll
            for (int k = 0; k < 2; k++) {
                int idx = tid + k * NT;
                int row = idx >> 3, c8 = idx & 7;
                int gr = rowBlock + row;
                uint4 u = (gr < NN) ? __ldcg(X4 + (size_t)gr * 8 + c8)
                                    : make_uint4(0u, 0u, 0u, 0u);
                *(uint4*)&xs[row * WT_STRIDE + c8 * 8] = u;
            }
        }
        __syncthreads();

        float c[4][4];
#pragma unroll
        for (int j = 0; j < 4; j++)
#pragma unroll
            for (int q = 0; q < 4; q++) c[j][q] = 0.f;
#pragma unroll
        for (int ks = 0; ks < 4; ks++) {
            int k0 = ks * 16;
            unsigned a0 = *(const unsigned*)&xs[(mt + qr) * WT_STRIDE + k0 + qc];
            unsigned a1 = *(const unsigned*)&xs[(mt + qr + 8) * WT_STRIDE + k0 + qc];
            unsigned a2 = *(const unsigned*)&xs[(mt + qr) * WT_STRIDE + k0 + qc + 8];
            unsigned a3 = *(const unsigned*)&xs[(mt + qr + 8) * WT_STRIDE + k0 + qc + 8];
#pragma unroll
            for (int j = 0; j < 4; j++) {
                int n = nb + j * 8 + qr;
                unsigned b0 = *(const unsigned*)&w1[n * WT_STRIDE + k0 + qc];
                unsigned b1 = *(const unsigned*)&w1[n * WT_STRIDE + k0 + qc + 8];
                asm volatile(
                    "mma.sync.aligned.m16n8k16.row.col.f32.f16.f16.f32 "
                    "{%0,%1,%2,%3}, {%4,%5,%6,%7}, {%8,%9}, {%0,%1,%2,%3};"
                    : "+f"(c[j][0]), "+f"(c[j][1]), "+f"(c[j][2]), "+f"(c[j][3])
                    : "r"(a0), "r"(a1), "r"(a2), "r"(a3), "r"(b0), "r"(b1));
            }
        }
        __syncthreads();
#pragma unroll
        for (int j = 0; j < 4; j++) {
            int n0 = nb + j * 8;
            float v0 = fmaxf(c[j][0] + bs1[n0 + qc], 0.f);
            float v1 = fmaxf(c[j][1] + bs1[n0 + qc + 1], 0.f);
            float v2 = fmaxf(c[j][2] + bs1[n0 + qc], 0.f);
            float v3 = fmaxf(c[j][3] + bs1[n0 + qc + 1], 0.f);
            *(__half2*)&xs[(mt + qr) * WT_STRIDE + n0 + qc] = __floats2half2_rn(v0, v1);
            *(__half2*)&xs[(mt + qr + 8) * WT_STRIDE + n0 + qc] = __floats2half2_rn(v2, v3);
        }
        __syncthreads();

        float d[4] = {0.f, 0.f, 0.f, 0.f};
        int n0 = (w & 1) * 8;
#pragma unroll
        for (int ks = 0; ks < 4; ks++) {
            int k0 = ks * 16;
            unsigned a0 = *(const unsigned*)&xs[(mt + qr) * WT_STRIDE + k0 + qc];
            unsigned a1 = *(const unsigned*)&xs[(mt + qr + 8) * WT_STRIDE + k0 + qc];
            unsigned a2 = *(const unsigned*)&xs[(mt + qr) * WT_STRIDE + k0 + qc + 8];
            unsigned a3 = *(const unsigned*)&xs[(mt + qr + 8) * WT_STRIDE + k0 + qc + 8];
            unsigned b0 = *(const unsigned*)&w2[(n0 + qr) * WT_STRIDE + k0 + qc];
            unsigned b1 = *(const unsigned*)&w2[(n0 + qr) * WT_STRIDE + k0 + qc + 8];
            asm volatile(
                "mma.sync.aligned.m16n8k16.row.col.f32.f16.f16.f32 "
                "{%0,%1,%2,%3}, {%4,%5,%6,%7}, {%8,%9}, {%0,%1,%2,%3};"
                : "+f"(d[0]), "+f"(d[1]), "+f"(d[2]), "+f"(d[3])
                : "r"(a0), "r"(a1), "r"(a2), "r"(a3), "r"(b0), "r"(b1));
        }
        int gr0 = rowBlock + mt + qr;
        int gr1 = gr0 + 8;
        if (gr0 < NN)
            *(float2*)&Y[(size_t)gr0 * 16 + n0 + qc] =
                make_float2(d[0] + bs2[n0 + qc], d[1] + bs2[n0 + qc + 1]);
        if (gr1 < NN)
            *(float2*)&Y[(size_t)gr1 * 16 + n0 + qc] =
                make_float2(d[2] + bs2[n0 + qc], d[3] + bs2[n0 + qc + 1]);
    }
}

// ---------------- mega kernel -------------------------------------------------
__global__ __launch_bounds__(NT, 1) void k_mega(
    const float* __restrict__ x, const int* __restrict__ ei,
    const float* __restrict__ W1, const float* __restrict__ b1,
    const float* __restrict__ W2, const float* __restrict__ b2,
    const float* __restrict__ W3, const float* __restrict__ b3,
    const float* __restrict__ Wf1, const float* __restrict__ bf1,
    const float* __restrict__ Wf2, const float* __restrict__ bf2,
    float* __restrict__ out) {
    extern __shared__ char sm[];
    int tid = threadIdx.x;
    int cta = blockIdx.x;
    int gtid = cta * NT + tid;
    int lane = tid & 31, wrp = tid >> 5;

    // ---- P0: weight prep + degree count ----
    for (int t = gtid; t < 4 * 4096 + 1024; t += GSZ) {
        if (t < 4 * 4096) {
            int w = t >> 12, i = t & 4095, k = i >> 6, n = i & 63;
            const float* src = (w == 0) ? W1 : (w == 1) ? W2 : (w == 2) ? W3 : Wf1;
            g_wt[w * WT_SZ + n * WT_STRIDE + k] = __float2half(src[k * 64 + n]);
        } else {
            int i = t - 4 * 4096;
            int k = i >> 4, n = i & 15;
            g_wt[4 * WT_SZ + n * WT_STRIDE + k] = __float2half(Wf2[k * 16 + n]);
        }
    }
    {
        const int4* d4 = (const int4*)(ei + EE);
        for (int t = gtid; t < EE / 4; t += GSZ) {
            int4 d = d4[t];
            atomicAdd(&g_deg[d.x], 1);
            atomicAdd(&g_deg[d.y], 1);
            atomicAdd(&g_deg[d.z], 1);
            atomicAdd(&g_deg[d.w], 1);
        }
    }
    gbar();

    // ---- P1: per-CTA inclusive scan over even-padded lengths ----
    __shared__ int wsum[32];
    __shared__ int s_ctaoff;
    int node = cta * CHUNK + tid;
    int dg = (tid < CHUNK && node < NN) ? g_deg[node] : 0;
    int pl = (dg + 1) & ~1;
    int incl = pl;
#pragma unroll
    for (int off = 1; off < 32; off <<= 1) {
        int t = __shfl_up_sync(0xFFFFFFFFu, incl, off);
        if (lane >= off) incl += t;
    }
    if (lane == 31) wsum[wrp] = incl;
    __syncthreads();
    if (wrp == 0) {
        int v = wsum[lane];
        int iv = v;
#pragma unroll
        for (int off = 1; off < 32; off <<= 1) {
            int t = __shfl_up_sync(0xFFFFFFFFu, iv, off);
            if (lane >= off) iv += t;
        }
        wsum[lane] = iv;
    }
    __syncthreads();
    if (wrp > 0) incl += wsum[wrp - 1];
    if (tid == 0) g_bsum[cta] = wsum[31];
    gbar();

    // ---- P2: cross-CTA offset + write off/cur/dinv ----
    {
        int v = (tid < cta) ? g_bsum[tid] : 0;
#pragma unroll
        for (int off = 16; off > 0; off >>= 1)
            v += __shfl_down_sync(0xFFFFFFFFu, v, off);
        __shared__ int rsum[32];
        if (lane == 0) rsum[wrp] = v;
        __syncthreads();
        if (tid == 0) {
            int t = 0;
#pragma unroll
            for (int i = 0; i < 32; i++) t += rsum[i];
            s_ctaoff = t;
        }
        __syncthreads();
    }
    int excl = s_ctaoff + incl - pl;
    if (tid < CHUNK && node < NN) {
        g_off[node] = excl;
        g_cur[node] = excl;
        g_dinv[node] = rsqrtf((float)dg + 1.0f);
    }
    if (cta == 0 && tid == 0) {
        int t = 0;
        for (int i = 0; i < NB; i++) t += g_bsum[i];
        g_off[NN] = t;
    }
    gbar();

    // ---- P3: fill CSR + pads + re-zero deg + convert x -> g_f (fp16) ----
    for (int e = gtid; e < EE; e += GSZ) {
        int s = ei[e];
        int d = ei[EE + e];
        int p = atomicAdd(&g_cur[d], 1);
        float c = g_dinv[s] * g_dinv[d];
        g_epack[p] = make_int2(s, __float_as_int(c));
    }
    for (int n = gtid; n < NN; n += GSZ) {
        int dg2 = g_deg[n];
        if (dg2 & 1) g_epack[g_off[n] + dg2] = make_int2(0, 0);
        g_deg[n] = 0;
    }
    {
        const float4* xin = (const float4*)x;
        uint2* xf = (uint2*)g_f;
        for (int i = gtid; i < NN * 16; i += GSZ) {
            float4 v = xin[i];
            __half2 h0 = __floats2half2_rn(v.x, v.y);
            __half2 h1 = __floats2half2_rn(v.z, v.w);
            uint2 u;
            u.x = *(unsigned*)&h0;
            u.y = *(unsigned*)&h1;
            xf[i] = u;
        }
    }
    gbar();

    // ---- layers (gemm reads g_f, writes g_h; agg reads g_h, writes g_f) ----
    gemm_phase(g_f, g_wt + 0 * WT_SZ, g_h, sm);
    gbar();
    agg_phase(g_h, g_f, b1);
    gbar();
    gemm_phase(g_f, g_wt + 1 * WT_SZ, g_h, sm);
    gbar();
    agg_phase(g_h, g_f, b2);
    gbar();
    gemm_phase(g_f, g_wt + 2 * WT_SZ, g_h, sm);
    gbar();
    agg_phase(g_h, g_f, b3);
    gbar();
    ffn_phase(g_f, g_wt + 3 * WT_SZ, g_wt + 4 * WT_SZ, bf1, bf2, out, sm);
}

// ---------------- launch ------------------------------------------------------
extern "C" void kernel_launch(void* const* d_in, const int* in_sizes, int n_in,
                              void* d_out, int out_size) {
    const float* x   = (const float*)d_in[0];
    const int*   ei  = (const int*)d_in[1];
    const float* W1  = (const float*)d_in[2];
    const float* b1  = (const float*)d_in[3];
    const float* W2  = (const float*)d_in[4];
    const float* b2  = (const float*)d_in[5];
    const float* W3  = (const float*)d_in[6];
    const float* b3  = (const float*)d_in[7];
    const float* Wf1 = (const float*)d_in[8];
    const float* bf1 = (const float*)d_in[9];
    const float* Wf2 = (const float*)d_in[10];
    const float* bf2 = (const float*)d_in[11];
    float* out = (float*)d_out;

    static bool attr_set = false;
    if (!attr_set) {
        cudaFuncSetAttribute(k_mega, cudaFuncAttributeMaxDynamicSharedMemorySize,
                             SM_TOTAL);
        attr_set = true;
    }
    k_mega<<<NB, NT, SM_TOTAL>>>(x, ei, W1, b1, W2, b2, W3, b3,
                                 Wf1, bf1, Wf2, bf2, out);
}

// round 16
// speedup vs baseline: 1.2555x; 1.0225x over previous
#include <cuda_runtime.h>
#include <cuda_fp16.h>

#define NN 100000
#define EE 1600000
#define NB 148
#define NT 1024
#define GSZ (NB * NT)
#define CHUNK 676            // ceil(NN/NB)
#define WT_STRIDE 72
#define WT_SZ (64 * WT_STRIDE)
#define W2_SZ (16 * WT_STRIDE)
#define TILE 256
#define NTILES 391           // ceil(NN/256)

// dynamic smem layout (bytes)
#define SM_XS0 0
#define SM_XS1 36864
#define SM_WT  73728
#define SM_W2  82944
#define SM_BS1 85248
#define SM_BS2 85504
#define SM_TOTAL 85568

// ---------------- device globals ---------------------------------------------
__device__ __half g_h[NN * 64];     // gemm out -> agg in
__device__ __half g_f[NN * 64];     // (converted x) / agg out -> gemm in
__device__ __half g_wt[5 * WT_SZ];
__device__ float  g_dinv[NN];
__device__ int    g_deg[NN];
__device__ int    g_off[NN + 1];
__device__ int4   g_tick4[EE / 4];  // per-edge insertion tickets (from P0 atomics)
#define g_tick ((int*)g_tick4)
// int4-typed: 16B-aligned base for LDG.128. One int4 = edge PAIR (s0,c0,s1,c1).
__device__ int4   g_epack4[(EE + NN) / 2 + 8];
#define g_epack ((int2*)g_epack4)
__device__ int    g_bsum[NB];
__device__ unsigned g_cnt;
__device__ volatile unsigned g_gen;

// ---------------- grid barrier ------------------------------------------------
__device__ __forceinline__ void gbar() {
    __syncthreads();
    if (threadIdx.x == 0) {
        unsigned gen = g_gen;
        __threadfence();
        unsigned t = atomicAdd(&g_cnt, 1u);
        if (t == NB - 1u) {
            g_cnt = 0u;
            __threadfence();
            g_gen = gen + 1u;
        } else {
            while (g_gen == gen) __nanosleep(32);
        }
    }
    __syncthreads();
}

// ---------------- warp 16x32 mma (rows mt.., cols nb..nb+31) ------------------
__device__ __forceinline__ void mma_16x32(const __half* xs, const __half* wt,
                                          __half* Y, int rowBlock,
                                          int mt, int nb, int qr, int qc) {
    float c[4][4];
#pragma unroll
    for (int j = 0; j < 4; j++)
#pragma unroll
        for (int q = 0; q < 4; q++) c[j][q] = 0.f;

#pragma unroll
    for (int ks = 0; ks < 4; ks++) {
        int k0 = ks * 16;
        unsigned a0 = *(const unsigned*)&xs[(mt + qr) * WT_STRIDE + k0 + qc];
        unsigned a1 = *(const unsigned*)&xs[(mt + qr + 8) * WT_STRIDE + k0 + qc];
        unsigned a2 = *(const unsigned*)&xs[(mt + qr) * WT_STRIDE + k0 + qc + 8];
        unsigned a3 = *(const unsigned*)&xs[(mt + qr + 8) * WT_STRIDE + k0 + qc + 8];
#pragma unroll
        for (int j = 0; j < 4; j++) {
            int n = nb + j * 8 + qr;
            unsigned b0 = *(const unsigned*)&wt[n * WT_STRIDE + k0 + qc];
            unsigned b1 = *(const unsigned*)&wt[n * WT_STRIDE + k0 + qc + 8];
            asm volatile(
                "mma.sync.aligned.m16n8k16.row.col.f32.f16.f16.f32 "
                "{%0,%1,%2,%3}, {%4,%5,%6,%7}, {%8,%9}, {%0,%1,%2,%3};"
                : "+f"(c[j][0]), "+f"(c[j][1]), "+f"(c[j][2]), "+f"(c[j][3])
                : "r"(a0), "r"(a1), "r"(a2), "r"(a3), "r"(b0), "r"(b1));
        }
    }
    int gr0 = rowBlock + mt + qr;
    int gr1 = gr0 + 8;
#pragma unroll
    for (int j = 0; j < 4; j++) {
        int n0 = nb + j * 8;
        if (gr0 < NN)
            *(__half2*)&Y[(size_t)gr0 * 64 + n0 + qc] = __floats2half2_rn(c[j][0], c[j][1]);
        if (gr1 < NN)
            *(__half2*)&Y[(size_t)gr1 * 64 + n0 + qc] = __floats2half2_rn(c[j][2], c[j][3]);
    }
}

// ---------------- gemm phase: fp16 in, 256-row tiles, double-buffered ---------
__device__ void gemm_phase(const __half* Xh, const __half* wtg, __half* Y, char* sm) {
    __half* xs0 = (__half*)(sm + SM_XS0);
    __half* xs1 = (__half*)(sm + SM_XS1);
    __half* wt  = (__half*)(sm + SM_WT);
    int tid = threadIdx.x;
    for (int i = tid; i < WT_SZ / 8; i += NT)
        ((uint4*)wt)[i] = ((const uint4*)wtg)[i];

    int lane = tid & 31, w = tid >> 5;
    int mt = (w >> 1) * 16;
    int nb = (w & 1) * 32;
    int qr = lane >> 2, qc = (lane & 3) * 2;

    const uint4* X4 = (const uint4*)Xh;
    int tile = blockIdx.x;
    if (tile < NTILES) {
#pragma unroll
        for (int k = 0; k < 2; k++) {
            int idx = tid + k * NT;
            int row = idx >> 3, c8 = idx & 7;
            int gr = tile * TILE + row;
            uint4 u = (gr < NN) ? __ldcg(X4 + (size_t)gr * 8 + c8)
                                : make_uint4(0u, 0u, 0u, 0u);
            *(uint4*)&xs0[row * WT_STRIDE + c8 * 8] = u;
        }
    }
    __syncthreads();

    int buf = 0;
    for (; tile < NTILES; tile += NB) {
        int nxt = tile + NB;
        bool has = nxt < NTILES;
        uint4 s16[2];
        if (has) {
#pragma unroll
            for (int k = 0; k < 2; k++) {
                int idx = tid + k * NT;
                int row = idx >> 3, c8 = idx & 7;
                int gr = nxt * TILE + row;
                s16[k] = (gr < NN) ? __ldcg(X4 + (size_t)gr * 8 + c8)
                                   : make_uint4(0u, 0u, 0u, 0u);
            }
        }
        const __half* cur = buf ? xs1 : xs0;
        mma_16x32(cur, wt, Y, tile * TILE, mt, nb, qr, qc);
        if (has) {
            __half* oth = buf ? xs0 : xs1;
#pragma unroll
            for (int k = 0; k < 2; k++) {
                int idx = tid + k * NT;
                int row = idx >> 3, c8 = idx & 7;
                *(uint4*)&oth[row * WT_STRIDE + c8 * 8] = s16[k];
            }
        }
        __syncthreads();
        buf ^= 1;
    }
}

// ---------------- agg: quarter-warp/node, uint4 rows, ep-prefetch pipeline ----
__device__ void agg_phase(const __half* h, __half* outp, const float* bias) {
    int gq = (blockIdx.x * NT + threadIdx.x) >> 3;
    int l8 = threadIdx.x & 7;
    const int NQ = GSZ / 8;

    for (int w = gq; w < NN; w += NQ) {
        int e0 = g_off[w];
        int npairs = (g_off[w + 1] - e0) >> 1;
        const int4* ep = g_epack4 + (e0 >> 1);
        float a0 = 0.f, a1 = 0.f, a2 = 0.f, a3 = 0.f;
        float a4 = 0.f, a5 = 0.f, a6 = 0.f, a7 = 0.f;

#define ACC(r, c) do {                                               \
            float2 f0 = __half22float2(*(__half2*)&(r).x);           \
            float2 f1 = __half22float2(*(__half2*)&(r).y);           \
            float2 f2 = __half22float2(*(__half2*)&(r).z);           \
            float2 f3 = __half22float2(*(__half2*)&(r).w);           \
            a0 = fmaf(f0.x, (c), a0); a1 = fmaf(f0.y, (c), a1);      \
            a2 = fmaf(f1.x, (c), a2); a3 = fmaf(f1.y, (c), a3);      \
            a4 = fmaf(f2.x, (c), a4); a5 = fmaf(f2.y, (c), a5);      \
            a6 = fmaf(f3.x, (c), a6); a7 = fmaf(f3.y, (c), a7);      \
        } while (0)

        if (npairs > 0) {
            int4 pA = ep[0];
            int4 pB = ep[(1 < npairs) ? 1 : 0];
            bool mB = 1 < npairs;
            int pc = 0;
            for (;;) {
                // issue current 4 row loads
                uint4 r0 = __ldcg((const uint4*)(h + (size_t)pA.x * 64) + l8);
                uint4 r1 = __ldcg((const uint4*)(h + (size_t)pA.z * 64) + l8);
                uint4 r2 = __ldcg((const uint4*)(h + (size_t)pB.x * 64) + l8);
                uint4 r3 = __ldcg((const uint4*)(h + (size_t)pB.z * 64) + l8);
                float c0 = __int_as_float(pA.y);      // pads carry coef 0
                float c1 = __int_as_float(pA.w);
                float c2 = mB ? __int_as_float(pB.y) : 0.f;
                float c3 = mB ? __int_as_float(pB.w) : 0.f;
                // prefetch next ep pair before consuming rows
                int nc = pc + 2;
                bool more = nc < npairs;
                int4 qA, qB;
                bool nmB = false;
                if (more) {
                    qA = ep[nc];
                    qB = ep[(nc + 1 < npairs) ? nc + 1 : nc];
                    nmB = nc + 1 < npairs;
                }
                ACC(r0, c0);
                ACC(r1, c1);
                ACC(r2, c2);
                ACC(r3, c3);
                if (!more) break;
                pA = qA; pB = qB; mB = nmB; pc = nc;
            }
        }

        float dn = g_dinv[w];
        float d2 = dn * dn;
        uint4 su = __ldcg((const uint4*)(h + (size_t)w * 64) + l8);
        ACC(su, d2);
#undef ACC
        float4 bA = ((const float4*)bias)[l8 * 2];
        float4 bB = ((const float4*)bias)[l8 * 2 + 1];
        a0 += bA.x; a1 += bA.y; a2 += bA.z; a3 += bA.w;
        a4 += bB.x; a5 += bB.y; a6 += bB.z; a7 += bB.w;
        __half2 h0 = __floats2half2_rn(fmaxf(a0, 0.f), fmaxf(a1, 0.f));
        __half2 h1 = __floats2half2_rn(fmaxf(a2, 0.f), fmaxf(a3, 0.f));
        __half2 h2 = __floats2half2_rn(fmaxf(a4, 0.f), fmaxf(a5, 0.f));
        __half2 h3 = __floats2half2_rn(fmaxf(a6, 0.f), fmaxf(a7, 0.f));
        uint4 o;
        o.x = *(unsigned*)&h0; o.y = *(unsigned*)&h1;
        o.z = *(unsigned*)&h2; o.w = *(unsigned*)&h3;
        *((uint4*)(outp + (size_t)w * 64) + l8) = o;
    }
}

// ---------------- ffn phase: 256-row tiles ------------------------------------
__device__ void ffn_phase(const __half* Xh, const __half* wt1g, const __half* wt2g,
                          const float* b1f, const float* b2f, float* Y, char* sm) {
    __half* xs = (__half*)(sm + SM_XS0);
    __half* w1 = (__half*)(sm + SM_WT);
    __half* w2 = (__half*)(sm + SM_W2);
    float* bs1 = (float*)(sm + SM_BS1);
    float* bs2 = (float*)(sm + SM_BS2);
    int tid = threadIdx.x;
    for (int i = tid; i < WT_SZ / 8; i += NT)
        ((uint4*)w1)[i] = ((const uint4*)wt1g)[i];
    if (tid < W2_SZ / 8) ((uint4*)w2)[tid] = ((const uint4*)wt2g)[tid];
    if (tid < 64) bs1[tid] = b1f[tid];
    if (tid < 16) bs2[tid] = b2f[tid];

    int lane = tid & 31, w = tid >> 5;
    int mt = (w >> 1) * 16;
    int nb = (w & 1) * 32;
    int qr = lane >> 2, qc = (lane & 3) * 2;

    for (int tile = blockIdx.x; tile < NTILES; tile += NB) {
        int rowBlock = tile * TILE;
        __syncthreads();
        {
            const uint4* X4 = (const uint4*)Xh;
#pragma unroll
            for (int k = 0; k < 2; k++) {
                int idx = tid + k * NT;
                int row = idx >> 3, c8 = idx & 7;
                int gr = rowBlock + row;
                uint4 u = (gr < NN) ? __ldcg(X4 + (size_t)gr * 8 + c8)
                                    : make_uint4(0u, 0u, 0u, 0u);
                *(uint4*)&xs[row * WT_STRIDE + c8 * 8] = u;
            }
        }
        __syncthreads();

        float c[4][4];
#pragma unroll
        for (int j = 0; j < 4; j++)
#pragma unroll
            for (int q = 0; q < 4; q++) c[j][q] = 0.f;
#pragma unroll
        for (int ks = 0; ks < 4; ks++) {
            int k0 = ks * 16;
            unsigned a0 = *(const unsigned*)&xs[(mt + qr) * WT_STRIDE + k0 + qc];
            unsigned a1 = *(const unsigned*)&xs[(mt + qr + 8) * WT_STRIDE + k0 + qc];
            unsigned a2 = *(const unsigned*)&xs[(mt + qr) * WT_STRIDE + k0 + qc + 8];
            unsigned a3 = *(const unsigned*)&xs[(mt + qr + 8) * WT_STRIDE + k0 + qc + 8];
#pragma unroll
            for (int j = 0; j < 4; j++) {
                int n = nb + j * 8 + qr;
                unsigned b0 = *(const unsigned*)&w1[n * WT_STRIDE + k0 + qc];
                unsigned b1 = *(const unsigned*)&w1[n * WT_STRIDE + k0 + qc + 8];
                asm volatile(
                    "mma.sync.aligned.m16n8k16.row.col.f32.f16.f16.f32 "
                    "{%0,%1,%2,%3}, {%4,%5,%6,%7}, {%8,%9}, {%0,%1,%2,%3};"
                    : "+f"(c[j][0]), "+f"(c[j][1]), "+f"(c[j][2]), "+f"(c[j][3])
                    : "r"(a0), "r"(a1), "r"(a2), "r"(a3), "r"(b0), "r"(b1));
            }
        }
        __syncthreads();
#pragma unroll
        for (int j = 0; j < 4; j++) {
            int n0 = nb + j * 8;
            float v0 = fmaxf(c[j][0] + bs1[n0 + qc], 0.f);
            float v1 = fmaxf(c[j][1] + bs1[n0 + qc + 1], 0.f);
            float v2 = fmaxf(c[j][2] + bs1[n0 + qc], 0.f);
            float v3 = fmaxf(c[j][3] + bs1[n0 + qc + 1], 0.f);
            *(__half2*)&xs[(mt + qr) * WT_STRIDE + n0 + qc] = __floats2half2_rn(v0, v1);
            *(__half2*)&xs[(mt + qr + 8) * WT_STRIDE + n0 + qc] = __floats2half2_rn(v2, v3);
        }
        __syncthreads();

        float d[4] = {0.f, 0.f, 0.f, 0.f};
        int n0 = (w & 1) * 8;
#pragma unroll
        for (int ks = 0; ks < 4; ks++) {
            int k0 = ks * 16;
            unsigned a0 = *(const unsigned*)&xs[(mt + qr) * WT_STRIDE + k0 + qc];
            unsigned a1 = *(const unsigned*)&xs[(mt + qr + 8) * WT_STRIDE + k0 + qc];
            unsigned a2 = *(const unsigned*)&xs[(mt + qr) * WT_STRIDE + k0 + qc + 8];
            unsigned a3 = *(const unsigned*)&xs[(mt + qr + 8) * WT_STRIDE + k0 + qc + 8];
            unsigned b0 = *(const unsigned*)&w2[(n0 + qr) * WT_STRIDE + k0 + qc];
            unsigned b1 = *(const unsigned*)&w2[(n0 + qr) * WT_STRIDE + k0 + qc + 8];
            asm volatile(
                "mma.sync.aligned.m16n8k16.row.col.f32.f16.f16.f32 "
                "{%0,%1,%2,%3}, {%4,%5,%6,%7}, {%8,%9}, {%0,%1,%2,%3};"
                : "+f"(d[0]), "+f"(d[1]), "+f"(d[2]), "+f"(d[3])
                : "r"(a0), "r"(a1), "r"(a2), "r"(a3), "r"(b0), "r"(b1));
        }
        int gr0 = rowBlock + mt + qr;
        int gr1 = gr0 + 8;
        if (gr0 < NN)
            *(float2*)&Y[(size_t)gr0 * 16 + n0 + qc] =
                make_float2(d[0] + bs2[n0 + qc], d[1] + bs2[n0 + qc + 1]);
        if (gr1 < NN)
            *(float2*)&Y[(size_t)gr1 * 16 + n0 + qc] =
                make_float2(d[2] + bs2[n0 + qc], d[3] + bs2[n0 + qc + 1]);
    }
}

// ---------------- mega kernel -------------------------------------------------
__global__ __launch_bounds__(NT, 1) void k_mega(
    const float* __restrict__ x, const int* __restrict__ ei,
    const float* __restrict__ W1, const float* __restrict__ b1,
    const float* __restrict__ W2, const float* __restrict__ b2,
    const float* __restrict__ W3, const float* __restrict__ b3,
    const float* __restrict__ Wf1, const float* __restrict__ bf1,
    const float* __restrict__ Wf2, const float* __restrict__ bf2,
    float* __restrict__ out) {
    extern __shared__ char sm[];
    int tid = threadIdx.x;
    int cta = blockIdx.x;
    int gtid = cta * NT + tid;
    int lane = tid & 31, wrp = tid >> 5;

    // ---- P0: weight prep + degree count (tickets) + x -> fp16 ----
    for (int t = gtid; t < 4 * 4096 + 1024; t += GSZ) {
        if (t < 4 * 4096) {
            int w = t >> 12, i = t & 4095, k = i >> 6, n = i & 63;
            const float* src = (w == 0) ? W1 : (w == 1) ? W2 : (w == 2) ? W3 : Wf1;
            g_wt[w * WT_SZ + n * WT_STRIDE + k] = __float2half(src[k * 64 + n]);
        } else {
            int i = t - 4 * 4096;
            int k = i >> 4, n = i & 15;
            g_wt[4 * WT_SZ + n * WT_STRIDE + k] = __float2half(Wf2[k * 16 + n]);
        }
    }
    {
        const int4* d4 = (const int4*)(ei + EE);
        for (int t = gtid; t < EE / 4; t += GSZ) {
            int4 d = d4[t];
            int t0 = atomicAdd(&g_deg[d.x], 1);
            int t1 = atomicAdd(&g_deg[d.y], 1);
            int t2 = atomicAdd(&g_deg[d.z], 1);
            int t3 = atomicAdd(&g_deg[d.w], 1);
            g_tick4[t] = make_int4(t0, t1, t2, t3);
        }
    }
    {
        const float4* xin = (const float4*)x;
        uint2* xf = (uint2*)g_f;
        for (int i = gtid; i < NN * 16; i += GSZ) {
            float4 v = xin[i];
            __half2 h0 = __floats2half2_rn(v.x, v.y);
            __half2 h1 = __floats2half2_rn(v.z, v.w);
            uint2 u;
            u.x = *(unsigned*)&h0;
            u.y = *(unsigned*)&h1;
            xf[i] = u;
        }
    }
    gbar();

    // ---- P1: per-CTA inclusive scan over even-padded lengths ----
    __shared__ int wsum[32];
    __shared__ int s_ctaoff;
    int node = cta * CHUNK + tid;
    int dg = (tid < CHUNK && node < NN) ? g_deg[node] : 0;
    int pl = (dg + 1) & ~1;
    int incl = pl;
#pragma unroll
    for (int off = 1; off < 32; off <<= 1) {
        int t = __shfl_up_sync(0xFFFFFFFFu, incl, off);
        if (lane >= off) incl += t;
    }
    if (lane == 31) wsum[wrp] = incl;
    __syncthreads();
    if (wrp == 0) {
        int v = wsum[lane];
        int iv = v;
#pragma unroll
        for (int off = 1; off < 32; off <<= 1) {
            int t = __shfl_up_sync(0xFFFFFFFFu, iv, off);
            if (lane >= off) iv += t;
        }
        wsum[lane] = iv;
    }
    __syncthreads();
    if (wrp > 0) incl += wsum[wrp - 1];
    if (tid == 0) g_bsum[cta] = wsum[31];
    gbar();

    // ---- P2: cross-CTA offset + write off/dinv ----
    {
        int v = (tid < cta) ? g_bsum[tid] : 0;
#pragma unroll
        for (int off = 16; off > 0; off >>= 1)
            v += __shfl_down_sync(0xFFFFFFFFu, v, off);
        __shared__ int rsum[32];
        if (lane == 0) rsum[wrp] = v;
        __syncthreads();
        if (tid == 0) {
            int t = 0;
#pragma unroll
            for (int i = 0; i < 32; i++) t += rsum[i];
            s_ctaoff = t;
        }
        __syncthreads();
    }
    int excl = s_ctaoff + incl - pl;
    if (tid < CHUNK && node < NN) {
        g_off[node] = excl;
        g_dinv[node] = rsqrtf((float)dg + 1.0f);
    }
    if (cta == 0 && tid == 0) {
        int t = 0;
        for (int i = 0; i < NB; i++) t += g_bsum[i];
        g_off[NN] = t;
    }
    gbar();

    // ---- P3: fill CSR via tickets (no atomics) + pads + re-zero deg ----
    for (int e = gtid; e < EE; e += GSZ) {
        int s = ei[e];
        int d = ei[EE + e];
        int p = g_off[d] + g_tick[e];
        float c = g_dinv[s] * g_dinv[d];
        g_epack[p] = make_int2(s, __float_as_int(c));
    }
    for (int n = gtid; n < NN; n += GSZ) {
        int dg2 = g_deg[n];
        if (dg2 & 1) g_epack[g_off[n] + dg2] = make_int2(0, 0);
        g_deg[n] = 0;
    }
    gbar();

    // ---- layers (gemm reads g_f, writes g_h; agg reads g_h, writes g_f) ----
    gemm_phase(g_f, g_wt + 0 * WT_SZ, g_h, sm);
    gbar();
    agg_phase(g_h, g_f, b1);
    gbar();
    gemm_phase(g_f, g_wt + 1 * WT_SZ, g_h, sm);
    gbar();
    agg_phase(g_h, g_f, b2);
    gbar();
    gemm_phase(g_f, g_wt + 2 * WT_SZ, g_h, sm);
    gbar();
    agg_phase(g_h, g_f, b3);
    gbar();
    ffn_phase(g_f, g_wt + 3 * WT_SZ, g_wt + 4 * WT_SZ, bf1, bf2, out, sm);
}

// ---------------- launch ------------------------------------------------------
extern "C" void kernel_launch(void* const* d_in, const int* in_sizes, int n_in,
                              void* d_out, int out_size) {
    const float* x   = (const float*)d_in[0];
    const int*   ei  = (const int*)d_in[1];
    const float* W1  = (const float*)d_in[2];
    const float* b1  = (const float*)d_in[3];
    const float* W2  = (const float*)d_in[4];
    const float* b2  = (const float*)d_in[5];
    const float* W3  = (const float*)d_in[6];
    const float* b3  = (const float*)d_in[7];
    const float* Wf1 = (const float*)d_in[8];
    const float* bf1 = (const float*)d_in[9];
    const float* Wf2 = (const float*)d_in[10];
    const float* bf2 = (const float*)d_in[11];
    float* out = (float*)d_out;

    static bool attr_set = false;
    if (!attr_set) {
        cudaFuncSetAttribute(k_mega, cudaFuncAttributeMaxDynamicSharedMemorySize,
                             SM_TOTAL);
        attr_set = true;
    }
    k_mega<<<NB, NT, SM_TOTAL>>>(x, ei, W1, b1, W2, b2, W3, b3,
                                 Wf1, bf1, Wf2, bf2, out);
}